// round 3
// baseline (speedup 1.0000x reference)
#include <cuda_runtime.h>

#define Bn 16
#define Cc 384
#define Hh 56
#define Ww 56
#define HW (Hh*Ww)
#define KL 31
#define KS 5
#define PL 15
#define XT 86          // 56 + 2*15
#define TS 92          // smem row stride in float2 elements (TS%8==4 -> conflict-free)
#define NTHREADS 448   // 56 row-groups (1 row) x 8 col-groups (7 cols)
#define NWARPS 14

typedef unsigned long long ull;

// Scratch (device globals: allocation-free rule)
__device__ float g_yL[(size_t)Bn*Cc*HW];
__device__ float g_yS[(size_t)Bn*Cc*HW];
__device__ float g_part[4][Cc][Bn];   // sumL, sumsqL, sumS, sumsqS
__device__ float g_coef[4][Cc];       // scaleL, biasL, scaleS, biasS

__device__ __forceinline__ ull f2fma(ull a, ull b, ull c) {
    ull d;
    asm("fma.rn.f32x2 %0, %1, %2, %3;" : "=l"(d) : "l"(a), "l"(b), "l"(c));
    return d;
}
__device__ __forceinline__ float2 u2f(ull v) {
    float2 f;
    asm("mov.b64 {%0, %1}, %2;" : "=f"(f.x), "=f"(f.y) : "l"(v));
    return f;
}
__device__ __forceinline__ ull f2u(float x, float y) {
    ull v;
    asm("mov.b64 %0, {%1, %2};" : "=l"(v) : "f"(x), "f"(y));
    return v;
}

// dynamic smem layout (bytes):
//   sx   : XT*TS ull        = 63296
//   swL2 : KL*KL ull        = 7688
//   swS2 : KS*KS ull        = 200
//   sred : 4*NWARPS float   = 224
#define SMEM_BYTES (XT*TS*8 + KL*KL*8 + KS*KS*8 + 4*NWARPS*4)

__global__ __launch_bounds__(NTHREADS, 3)
void conv_kernel(const float* __restrict__ x,
                 const float* __restrict__ wL,
                 const float* __restrict__ wS)
{
    extern __shared__ ull dyn[];
    ull* sx   = dyn;                 // [XT*TS] interleaved {imgA, imgB}
    ull* swL2 = sx + XT*TS;          // [KL*KL] {w,w}
    ull* swS2 = swL2 + KL*KL;        // [KS*KS] {w,w}
    float* sred = (float*)(swS2 + KS*KS);  // [4][NWARPS]

    const int blk = blockIdx.x;
    const int c  = blk % Cc;
    const int np = blk / Cc;
    const int nA = np*2;
    const int tid = threadIdx.x;

    // stage weights duplicated {w,w}
    for (int i = tid; i < KL*KL; i += NTHREADS) {
        float w = wL[c*KL*KL + i];
        swL2[i] = f2u(w, w);
    }
    if (tid < KS*KS) {
        float w = wS[c*KS*KS + tid];
        swS2[tid] = f2u(w, w);
    }

    // stage both image slices interleaved, zero halo
    const float* __restrict__ xA = x + (size_t)(nA*Cc + c)*HW;
    const float* __restrict__ xB = xA + (size_t)Cc*HW;
    for (int i = tid; i < XT*TS; i += NTHREADS) {
        int r = i / TS, col = i % TS;
        int gy = r - PL, gx = col - PL;
        float a = 0.f, b = 0.f;
        if (col < XT && gy >= 0 && gy < Hh && gx >= 0 && gx < Ww) {
            a = xA[gy*Ww + gx];
            b = xB[gy*Ww + gx];
        }
        sx[i] = f2u(a, b);
    }
    __syncthreads();

    const int ty = tid >> 3;       // 0..55  (one output row per thread)
    const int tx = tid & 7;        // 0..7   (7 output cols per thread)
    const int oy0 = ty, ox0 = tx*7;
    const int wid = tid >> 5, lane = tid & 31;

    // ---------------- large 31x31 conv (packed over 2 images) ----------------
    ull acc[7];
#pragma unroll
    for (int j = 0; j < 7; j++) acc[j] = 0ULL;

#pragma unroll 1
    for (int ky = 0; ky < KL; ky++) {
        const ull* __restrict__ r0 = sx + (oy0 + ky)*TS + ox0;
        const ull* __restrict__ wr = swL2 + ky*KL;

        ull win[8];
#pragma unroll
        for (int j = 0; j < 7; j++) win[j] = r0[j];
        ull wcur = wr[0];
#pragma unroll
        for (int kx = 0; kx < KL; kx++) {
            ull wnext = (kx < KL-1) ? wr[kx+1] : 0ULL;
#pragma unroll
            for (int j = 0; j < 7; j++) {
                acc[j] = f2fma(win[(kx + j) & 7], wcur, acc[j]);
            }
            if (kx < KL-1) win[(kx+7)&7] = r0[kx+7];
            wcur = wnext;
        }
    }

    // write yL (both images) + per-block stats
    {
        float* __restrict__ ypA = g_yL + (size_t)(nA*Cc + c)*HW + oy0*Ww + ox0;
        float* __restrict__ ypB = ypA + (size_t)Cc*HW;
        float sA = 0.f, qA = 0.f, sB = 0.f, qB = 0.f;
#pragma unroll
        for (int j = 0; j < 7; j++) {
            float2 v = u2f(acc[j]);
            ypA[j] = v.x;
            ypB[j] = v.y;
            sA += v.x;  qA += v.x*v.x;
            sB += v.y;  qB += v.y*v.y;
        }
#pragma unroll
        for (int o = 16; o; o >>= 1) {
            sA += __shfl_down_sync(0xFFFFFFFFu, sA, o);
            qA += __shfl_down_sync(0xFFFFFFFFu, qA, o);
            sB += __shfl_down_sync(0xFFFFFFFFu, sB, o);
            qB += __shfl_down_sync(0xFFFFFFFFu, qB, o);
        }
        if (lane == 0) {
            sred[0*NWARPS + wid] = sA;
            sred[1*NWARPS + wid] = qA;
            sred[2*NWARPS + wid] = sB;
            sred[3*NWARPS + wid] = qB;
        }
        __syncthreads();
        if (tid == 0) {
            float SA=0,QA=0,SB=0,QB=0;
            for (int i = 0; i < NWARPS; i++) {
                SA += sred[0*NWARPS+i]; QA += sred[1*NWARPS+i];
                SB += sred[2*NWARPS+i]; QB += sred[3*NWARPS+i];
            }
            g_part[0][c][nA]   = SA;  g_part[1][c][nA]   = QA;
            g_part[0][c][nA+1] = SB;  g_part[1][c][nA+1] = QB;
        }
        __syncthreads();   // sred reused below
    }

    // ---------------- small 5x5 conv (packed, same ring scheme) ----------------
    ull bcc[7];
#pragma unroll
    for (int j = 0; j < 7; j++) bcc[j] = 0ULL;

#pragma unroll
    for (int ky = 0; ky < KS; ky++) {
        // out(oy,ox) needs x[oy+ky-2][ox+kx-2] -> smem row oy+ky+13, col ox+kx+13
        const ull* __restrict__ r0 = sx + (oy0 + ky + 13)*TS + ox0 + 13;
        const ull* __restrict__ wr = swS2 + ky*KS;

        ull win[8];
#pragma unroll
        for (int j = 0; j < 7; j++) win[j] = r0[j];
        ull wcur = wr[0];
#pragma unroll
        for (int kx = 0; kx < KS; kx++) {
            ull wnext = (kx < KS-1) ? wr[kx+1] : 0ULL;
#pragma unroll
            for (int j = 0; j < 7; j++) {
                bcc[j] = f2fma(win[(kx + j) & 7], wcur, bcc[j]);
            }
            if (kx < KS-1) win[(kx+7)&7] = r0[kx+7];
            wcur = wnext;
        }
    }

    // write yS + per-block stats
    {
        float* __restrict__ ypA = g_yS + (size_t)(nA*Cc + c)*HW + oy0*Ww + ox0;
        float* __restrict__ ypB = ypA + (size_t)Cc*HW;
        float sA = 0.f, qA = 0.f, sB = 0.f, qB = 0.f;
#pragma unroll
        for (int j = 0; j < 7; j++) {
            float2 v = u2f(bcc[j]);
            ypA[j] = v.x;
            ypB[j] = v.y;
            sA += v.x;  qA += v.x*v.x;
            sB += v.y;  qB += v.y*v.y;
        }
#pragma unroll
        for (int o = 16; o; o >>= 1) {
            sA += __shfl_down_sync(0xFFFFFFFFu, sA, o);
            qA += __shfl_down_sync(0xFFFFFFFFu, qA, o);
            sB += __shfl_down_sync(0xFFFFFFFFu, sB, o);
            qB += __shfl_down_sync(0xFFFFFFFFu, qB, o);
        }
        if (lane == 0) {
            sred[0*NWARPS + wid] = sA;
            sred[1*NWARPS + wid] = qA;
            sred[2*NWARPS + wid] = sB;
            sred[3*NWARPS + wid] = qB;
        }
        __syncthreads();
        if (tid == 0) {
            float SA=0,QA=0,SB=0,QB=0;
            for (int i = 0; i < NWARPS; i++) {
                SA += sred[0*NWARPS+i]; QA += sred[1*NWARPS+i];
                SB += sred[2*NWARPS+i]; QB += sred[3*NWARPS+i];
            }
            g_part[2][c][nA]   = SA;  g_part[3][c][nA]   = QA;
            g_part[2][c][nA+1] = SB;  g_part[3][c][nA+1] = QB;
        }
    }
}

__global__ void stats_kernel(const float* __restrict__ gammaL, const float* __restrict__ betaL,
                             const float* __restrict__ gammaS, const float* __restrict__ betaS)
{
    int c = blockIdx.x*blockDim.x + threadIdx.x;
    if (c >= Cc) return;
    const float Nf = (float)(Bn*HW);
    float sL = 0.f, qL = 0.f, sS = 0.f, qS = 0.f;
#pragma unroll
    for (int n = 0; n < Bn; n++) {
        sL += g_part[0][c][n]; qL += g_part[1][c][n];
        sS += g_part[2][c][n]; qS += g_part[3][c][n];
    }
    float mL = sL / Nf, vL = qL / Nf - mL*mL;
    float invL = rsqrtf(vL + 1e-5f);
    float scL = gammaL[c] * invL;
    g_coef[0][c] = scL;
    g_coef[1][c] = betaL[c] - mL*scL;

    float mS = sS / Nf, vS = qS / Nf - mS*mS;
    float invS = rsqrtf(vS + 1e-5f);
    float scS = gammaS[c] * invS;
    g_coef[2][c] = scS;
    g_coef[3][c] = betaS[c] - mS*scS;
}

__global__ void norm_kernel(float* __restrict__ out)
{
    const int total4 = Bn*Cc*HW/4;
    int i = blockIdx.x*blockDim.x + threadIdx.x;
    if (i >= total4) return;
    const int c = (i / (HW/4)) % Cc;
    const float4 a = reinterpret_cast<const float4*>(g_yL)[i];
    const float4 b = reinterpret_cast<const float4*>(g_yS)[i];
    const float scL = g_coef[0][c], bL = g_coef[1][c];
    const float scS = g_coef[2][c], bS = g_coef[3][c];
    float4 o;
    o.x = fmaf(a.x, scL, bL) + fmaf(b.x, scS, bS);
    o.y = fmaf(a.y, scL, bL) + fmaf(b.y, scS, bS);
    o.z = fmaf(a.z, scL, bL) + fmaf(b.z, scS, bS);
    o.w = fmaf(a.w, scL, bL) + fmaf(b.w, scS, bS);
    reinterpret_cast<float4*>(out)[i] = o;
}

extern "C" void kernel_launch(void* const* d_in, const int* in_sizes, int n_in,
                              void* d_out, int out_size)
{
    const float* x       = (const float*)d_in[0];
    const float* w_large = (const float*)d_in[1];
    const float* gammaL  = (const float*)d_in[2];
    const float* betaL   = (const float*)d_in[3];
    const float* w_small = (const float*)d_in[4];
    const float* gammaS  = (const float*)d_in[5];
    const float* betaS   = (const float*)d_in[6];
    float* out = (float*)d_out;

    cudaFuncSetAttribute(conv_kernel, cudaFuncAttributeMaxDynamicSharedMemorySize, SMEM_BYTES);
    conv_kernel<<<(Bn/2)*Cc, NTHREADS, SMEM_BYTES>>>(x, w_large, w_small);
    stats_kernel<<<(Cc + 127)/128, 128>>>(gammaL, betaL, gammaS, betaS);
    const int total4 = Bn*Cc*HW/4;
    norm_kernel<<<(total4 + 255)/256, 256>>>(out);
}

// round 4
// speedup vs baseline: 1.2108x; 1.2108x over previous
#include <cuda_runtime.h>

#define Bn 16
#define Cc 384
#define Hh 56
#define Ww 56
#define HW (Hh*Ww)
#define KL 31
#define KS 5
#define PL 15
#define XT 86          // 56 + 2*15
#define TS 91          // odd stride -> warp (consecutive rows) hits all bank-pairs uniformly
#define SXN 7828       // 86*91 = 7826, padded to even (16B alignment for what follows)
#define WLN (KL*32)    // weight rows padded to 32 -> 16B-aligned pair loads
#define NTHREADS 224   // 56 rows x 4 col-groups of 14 cols
#define NWARPS 7

typedef unsigned long long ull;

// Scratch (device globals: allocation-free rule)
__device__ float g_yL[(size_t)Bn*Cc*HW];
__device__ float g_yS[(size_t)Bn*Cc*HW];
__device__ float g_part[4][Cc][Bn];   // sumL, sumsqL, sumS, sumsqS
__device__ float g_coef[4][Cc];       // scaleL, biasL, scaleS, biasS

__device__ __forceinline__ ull f2fma(ull a, ull b, ull c) {
    ull d;
    asm("fma.rn.f32x2 %0, %1, %2, %3;" : "=l"(d) : "l"(a), "l"(b), "l"(c));
    return d;
}
__device__ __forceinline__ float2 u2f(ull v) {
    float2 f;
    asm("mov.b64 {%0, %1}, %2;" : "=f"(f.x), "=f"(f.y) : "l"(v));
    return f;
}
__device__ __forceinline__ ull f2u(float x, float y) {
    ull v;
    asm("mov.b64 %0, {%1, %2};" : "=l"(v) : "f"(x), "f"(y));
    return v;
}

// dynamic smem (ull units): sx[SXN], swL2[WLN], swS2[25], sred
#define SMEM_BYTES (SXN*8 + WLN*8 + 25*8 + 4*NWARPS*4)

__global__ __launch_bounds__(NTHREADS, 3)
void conv_kernel(const float* __restrict__ x,
                 const float* __restrict__ wL,
                 const float* __restrict__ wS)
{
    extern __shared__ ull dyn[];
    ull* sx   = dyn;                  // [SXN] interleaved {imgA, imgB}
    ull* swL2 = sx + SXN;             // [KL*32] {w,w}, row-padded to 32
    ull* swS2 = swL2 + WLN;           // [25] {w,w}
    float* sred = (float*)(swS2 + 25);

    const int blk = blockIdx.x;
    const int c  = blk % Cc;
    const int np = blk / Cc;
    const int nA = np*2;
    const int tid = threadIdx.x;

    // stage large weights duplicated {w,w}, padded row stride 32 (slot 31 zeroed)
    for (int i = tid; i < WLN; i += NTHREADS) {
        int ky = i >> 5, kx = i & 31;
        float w = (kx < KL) ? wL[c*KL*KL + ky*KL + kx] : 0.f;
        swL2[i] = f2u(w, w);
    }
    if (tid < KS*KS) {
        float w = wS[c*KS*KS + tid];
        swS2[tid] = f2u(w, w);
    }

    // stage both image slices interleaved, zero halo
    const float* __restrict__ xA = x + (size_t)(nA*Cc + c)*HW;
    const float* __restrict__ xB = xA + (size_t)Cc*HW;
    for (int i = tid; i < XT*TS; i += NTHREADS) {
        int r = i / TS, col = i % TS;
        int gy = r - PL, gx = col - PL;
        float a = 0.f, b = 0.f;
        if (col < XT && gy >= 0 && gy < Hh && gx >= 0 && gx < Ww) {
            a = xA[gy*Ww + gx];
            b = xB[gy*Ww + gx];
        }
        sx[i] = f2u(a, b);
    }
    __syncthreads();

    const int ty = tid % 56;       // output row (warp = 32 consecutive rows)
    const int tx = tid / 56;       // 0..3 col-group
    const int oy0 = ty, ox0 = tx*14;
    const int wid = tid >> 5, lane = tid & 31;

    // ---------------- large 31x31 conv: 1 row x 14 cols, packed over 2 images ----------------
    ull acc[14];
#pragma unroll
    for (int j = 0; j < 14; j++) acc[j] = 0ULL;

#pragma unroll 1
    for (int ky = 0; ky < KL; ky++) {
        const ull* __restrict__ r0 = sx + (oy0 + ky)*TS + ox0;
        const ulonglong2* __restrict__ wr2 =
            reinterpret_cast<const ulonglong2*>(swL2 + ky*32);

        ull win[16];
#pragma unroll
        for (int j = 0; j < 14; j++) win[j] = r0[j];

        ulonglong2 wp = wr2[0];                 // {w0, w1}
#pragma unroll
        for (int kx = 0; kx < KL; kx += 2) {
            const ull wc0 = wp.x;
            const ull wc1 = wp.y;
            if (kx + 2 < KL) wp = wr2[(kx + 2) >> 1];   // prefetch next pair

            // body kx
#pragma unroll
            for (int j = 0; j < 14; j++)
                acc[j] = f2fma(win[(kx + j) & 15], wc0, acc[j]);
            if (kx <= 29) win[(kx + 14) & 15] = r0[kx + 14];

            // body kx+1 (kx=30 is the last, odd partner doesn't exist)
            if (kx + 1 < KL) {
#pragma unroll
                for (int j = 0; j < 14; j++)
                    acc[j] = f2fma(win[(kx + 1 + j) & 15], wc1, acc[j]);
                if (kx + 1 <= 29) win[(kx + 15) & 15] = r0[kx + 15];
            }
        }
    }

    // write yL (both images, packed STG.64) + per-block stats
    {
        float* __restrict__ ypA = g_yL + (size_t)(nA*Cc + c)*HW + oy0*Ww + ox0;
        float* __restrict__ ypB = ypA + (size_t)Cc*HW;
        float sA = 0.f, qA = 0.f, sB = 0.f, qB = 0.f;
#pragma unroll
        for (int j = 0; j < 14; j += 2) {
            float2 v0 = u2f(acc[j]);
            float2 v1 = u2f(acc[j+1]);
            *reinterpret_cast<ull*>(ypA + j) = f2u(v0.x, v1.x);
            *reinterpret_cast<ull*>(ypB + j) = f2u(v0.y, v1.y);
            sA += v0.x + v1.x;  qA += v0.x*v0.x + v1.x*v1.x;
            sB += v0.y + v1.y;  qB += v0.y*v0.y + v1.y*v1.y;
        }
#pragma unroll
        for (int o = 16; o; o >>= 1) {
            sA += __shfl_down_sync(0xFFFFFFFFu, sA, o);
            qA += __shfl_down_sync(0xFFFFFFFFu, qA, o);
            sB += __shfl_down_sync(0xFFFFFFFFu, sB, o);
            qB += __shfl_down_sync(0xFFFFFFFFu, qB, o);
        }
        if (lane == 0) {
            sred[0*NWARPS + wid] = sA;
            sred[1*NWARPS + wid] = qA;
            sred[2*NWARPS + wid] = sB;
            sred[3*NWARPS + wid] = qB;
        }
        __syncthreads();
        if (tid == 0) {
            float SA=0,QA=0,SB=0,QB=0;
            for (int i = 0; i < NWARPS; i++) {
                SA += sred[0*NWARPS+i]; QA += sred[1*NWARPS+i];
                SB += sred[2*NWARPS+i]; QB += sred[3*NWARPS+i];
            }
            g_part[0][c][nA]   = SA;  g_part[1][c][nA]   = QA;
            g_part[0][c][nA+1] = SB;  g_part[1][c][nA+1] = QB;
        }
        __syncthreads();   // sred reused below
    }

    // ---------------- small 5x5 conv: direct 18-wide window ----------------
    ull bcc[14];
#pragma unroll
    for (int j = 0; j < 14; j++) bcc[j] = 0ULL;

#pragma unroll
    for (int ky = 0; ky < KS; ky++) {
        // out col ox0+j needs smem col ox0 + j + kx + 13
        const ull* __restrict__ r0 = sx + (oy0 + ky + 13)*TS + ox0 + 13;
        const ull* __restrict__ wr = swS2 + ky*KS;
        ull v[18];
#pragma unroll
        for (int j = 0; j < 18; j++) v[j] = r0[j];
#pragma unroll
        for (int kx = 0; kx < KS; kx++) {
            const ull w = wr[kx];
#pragma unroll
            for (int j = 0; j < 14; j++)
                bcc[j] = f2fma(v[kx + j], w, bcc[j]);
        }
    }

    // write yS + per-block stats
    {
        float* __restrict__ ypA = g_yS + (size_t)(nA*Cc + c)*HW + oy0*Ww + ox0;
        float* __restrict__ ypB = ypA + (size_t)Cc*HW;
        float sA = 0.f, qA = 0.f, sB = 0.f, qB = 0.f;
#pragma unroll
        for (int j = 0; j < 14; j += 2) {
            float2 v0 = u2f(bcc[j]);
            float2 v1 = u2f(bcc[j+1]);
            *reinterpret_cast<ull*>(ypA + j) = f2u(v0.x, v1.x);
            *reinterpret_cast<ull*>(ypB + j) = f2u(v0.y, v1.y);
            sA += v0.x + v1.x;  qA += v0.x*v0.x + v1.x*v1.x;
            sB += v0.y + v1.y;  qB += v0.y*v0.y + v1.y*v1.y;
        }
#pragma unroll
        for (int o = 16; o; o >>= 1) {
            sA += __shfl_down_sync(0xFFFFFFFFu, sA, o);
            qA += __shfl_down_sync(0xFFFFFFFFu, qA, o);
            sB += __shfl_down_sync(0xFFFFFFFFu, sB, o);
            qB += __shfl_down_sync(0xFFFFFFFFu, qB, o);
        }
        if (lane == 0) {
            sred[0*NWARPS + wid] = sA;
            sred[1*NWARPS + wid] = qA;
            sred[2*NWARPS + wid] = sB;
            sred[3*NWARPS + wid] = qB;
        }
        __syncthreads();
        if (tid == 0) {
            float SA=0,QA=0,SB=0,QB=0;
            for (int i = 0; i < NWARPS; i++) {
                SA += sred[0*NWARPS+i]; QA += sred[1*NWARPS+i];
                SB += sred[2*NWARPS+i]; QB += sred[3*NWARPS+i];
            }
            g_part[2][c][nA]   = SA;  g_part[3][c][nA]   = QA;
            g_part[2][c][nA+1] = SB;  g_part[3][c][nA+1] = QB;
        }
    }
}

__global__ void stats_kernel(const float* __restrict__ gammaL, const float* __restrict__ betaL,
                             const float* __restrict__ gammaS, const float* __restrict__ betaS)
{
    int c = blockIdx.x*blockDim.x + threadIdx.x;
    if (c >= Cc) return;
    const float Nf = (float)(Bn*HW);
    float sL = 0.f, qL = 0.f, sS = 0.f, qS = 0.f;
#pragma unroll
    for (int n = 0; n < Bn; n++) {
        sL += g_part[0][c][n]; qL += g_part[1][c][n];
        sS += g_part[2][c][n]; qS += g_part[3][c][n];
    }
    float mL = sL / Nf, vL = qL / Nf - mL*mL;
    float invL = rsqrtf(vL + 1e-5f);
    float scL = gammaL[c] * invL;
    g_coef[0][c] = scL;
    g_coef[1][c] = betaL[c] - mL*scL;

    float mS = sS / Nf, vS = qS / Nf - mS*mS;
    float invS = rsqrtf(vS + 1e-5f);
    float scS = gammaS[c] * invS;
    g_coef[2][c] = scS;
    g_coef[3][c] = betaS[c] - mS*scS;
}

__global__ void norm_kernel(float* __restrict__ out)
{
    const int total4 = Bn*Cc*HW/4;
    int i = blockIdx.x*blockDim.x + threadIdx.x;
    if (i >= total4) return;
    const int c = (i / (HW/4)) % Cc;
    const float4 a = reinterpret_cast<const float4*>(g_yL)[i];
    const float4 b = reinterpret_cast<const float4*>(g_yS)[i];
    const float scL = g_coef[0][c], bL = g_coef[1][c];
    const float scS = g_coef[2][c], bS = g_coef[3][c];
    float4 o;
    o.x = fmaf(a.x, scL, bL) + fmaf(b.x, scS, bS);
    o.y = fmaf(a.y, scL, bL) + fmaf(b.y, scS, bS);
    o.z = fmaf(a.z, scL, bL) + fmaf(b.z, scS, bS);
    o.w = fmaf(a.w, scL, bL) + fmaf(b.w, scS, bS);
    reinterpret_cast<float4*>(out)[i] = o;
}

extern "C" void kernel_launch(void* const* d_in, const int* in_sizes, int n_in,
                              void* d_out, int out_size)
{
    const float* x       = (const float*)d_in[0];
    const float* w_large = (const float*)d_in[1];
    const float* gammaL  = (const float*)d_in[2];
    const float* betaL   = (const float*)d_in[3];
    const float* w_small = (const float*)d_in[4];
    const float* gammaS  = (const float*)d_in[5];
    const float* betaS   = (const float*)d_in[6];
    float* out = (float*)d_out;

    cudaFuncSetAttribute(conv_kernel, cudaFuncAttributeMaxDynamicSharedMemorySize, SMEM_BYTES);
    conv_kernel<<<(Bn/2)*Cc, NTHREADS, SMEM_BYTES>>>(x, w_large, w_small);
    stats_kernel<<<(Cc + 127)/128, 128>>>(gammaL, betaL, gammaS, betaS);
    const int total4 = Bn*Cc*HW/4;
    norm_kernel<<<(total4 + 255)/256, 256>>>(out);
}

// round 5
// speedup vs baseline: 1.2135x; 1.0022x over previous
#include <cuda_runtime.h>

#define Bn 16
#define Cc 384
#define Hh 56
#define Ww 56
#define HW (Hh*Ww)
#define KL 31
#define KS 5
#define PL 15
#define XT 86          // 56 + 2*15
#define TS 91          // odd stride -> warp (consecutive rows) hits all bank-pairs uniformly
#define SXN 7828       // 86*91 = 7826, padded to even (16B alignment for what follows)
#define WLN (KL*32)    // weight rows padded to 32 -> 16B-aligned pair loads
#define NTHREADS 224   // 56 rows x 4 col-groups of 14 cols
#define NWARPS 7

typedef unsigned long long ull;

// Scratch (device globals: allocation-free rule)
__device__ float g_yL[(size_t)Bn*Cc*HW];
__device__ float g_yS[(size_t)Bn*Cc*HW];
__device__ float g_part[4][Cc][Bn];   // sumL, sumsqL, sumS, sumsqS
__device__ float g_coef[4][Cc];       // scaleL, biasL, scaleS, biasS

__device__ __forceinline__ ull f2fma(ull a, ull b, ull c) {
    ull d;
    asm("fma.rn.f32x2 %0, %1, %2, %3;" : "=l"(d) : "l"(a), "l"(b), "l"(c));
    return d;
}
__device__ __forceinline__ float2 u2f(ull v) {
    float2 f;
    asm("mov.b64 {%0, %1}, %2;" : "=f"(f.x), "=f"(f.y) : "l"(v));
    return f;
}
__device__ __forceinline__ ull f2u(float x, float y) {
    ull v;
    asm("mov.b64 %0, {%1, %2};" : "=l"(v) : "f"(x), "f"(y));
    return v;
}

// dynamic smem (ull units): sx[SXN], swL2[WLN], swS2[25], sred
#define SMEM_BYTES (SXN*8 + WLN*8 + 25*8 + 4*NWARPS*4)

__global__ __launch_bounds__(NTHREADS, 3)
void conv_kernel(const float* __restrict__ x,
                 const float* __restrict__ wL,
                 const float* __restrict__ wS)
{
    extern __shared__ ull dyn[];
    ull* sx   = dyn;                  // [SXN] interleaved {imgA, imgB}
    ull* swL2 = sx + SXN;             // [KL*32] {w,w}, row-padded to 32
    ull* swS2 = swL2 + WLN;           // [25] {w,w}
    float* sred = (float*)(swS2 + 25);

    const int blk = blockIdx.x;
    const int c  = blk % Cc;
    const int np = blk / Cc;
    const int nA = np*2;
    const int tid = threadIdx.x;

    // stage large weights duplicated {w,w}, padded row stride 32 (slot 31 zeroed)
    for (int i = tid; i < WLN; i += NTHREADS) {
        int ky = i >> 5, kx = i & 31;
        float w = (kx < KL) ? wL[c*KL*KL + ky*KL + kx] : 0.f;
        swL2[i] = f2u(w, w);
    }
    if (tid < KS*KS) {
        float w = wS[c*KS*KS + tid];
        swS2[tid] = f2u(w, w);
    }

    // stage both image slices interleaved, zero halo
    const float* __restrict__ xA = x + (size_t)(nA*Cc + c)*HW;
    const float* __restrict__ xB = xA + (size_t)Cc*HW;
    for (int i = tid; i < XT*TS; i += NTHREADS) {
        int r = i / TS, col = i % TS;
        int gy = r - PL, gx = col - PL;
        float a = 0.f, b = 0.f;
        if (col < XT && gy >= 0 && gy < Hh && gx >= 0 && gx < Ww) {
            a = xA[gy*Ww + gx];
            b = xB[gy*Ww + gx];
        }
        sx[i] = f2u(a, b);
    }
    __syncthreads();

    const int ty = tid % 56;       // output row (warp = 32 consecutive rows)
    const int tx = tid / 56;       // 0..3 col-group
    const int oy0 = ty, ox0 = tx*14;
    const int wid = tid >> 5, lane = tid & 31;

    // ---------------- large 31x31 conv: 1 row x 14 cols, packed over 2 images ----------------
    ull acc[14];
#pragma unroll
    for (int j = 0; j < 14; j++) acc[j] = 0ULL;

#pragma unroll 1
    for (int ky = 0; ky < KL; ky++) {
        const ull* __restrict__ r0 = sx + (oy0 + ky)*TS + ox0;
        const ulonglong2* __restrict__ wr2 =
            reinterpret_cast<const ulonglong2*>(swL2 + ky*32);

        ull win[16];
#pragma unroll
        for (int j = 0; j < 14; j++) win[j] = r0[j];

        ulonglong2 wp = wr2[0];                 // {w0, w1}
#pragma unroll
        for (int kx = 0; kx < KL; kx += 2) {
            const ull wc0 = wp.x;
            const ull wc1 = wp.y;
            if (kx + 2 < KL) wp = wr2[(kx + 2) >> 1];   // prefetch next pair

            // body kx
#pragma unroll
            for (int j = 0; j < 14; j++)
                acc[j] = f2fma(win[(kx + j) & 15], wc0, acc[j]);
            if (kx <= 29) win[(kx + 14) & 15] = r0[kx + 14];

            // body kx+1 (kx=30 is the last, odd partner doesn't exist)
            if (kx + 1 < KL) {
#pragma unroll
                for (int j = 0; j < 14; j++)
                    acc[j] = f2fma(win[(kx + 1 + j) & 15], wc1, acc[j]);
                if (kx + 1 <= 29) win[(kx + 15) & 15] = r0[kx + 15];
            }
        }
    }

    // write yL (both images, packed STG.64) + per-block stats
    {
        float* __restrict__ ypA = g_yL + (size_t)(nA*Cc + c)*HW + oy0*Ww + ox0;
        float* __restrict__ ypB = ypA + (size_t)Cc*HW;
        float sA = 0.f, qA = 0.f, sB = 0.f, qB = 0.f;
#pragma unroll
        for (int j = 0; j < 14; j += 2) {
            float2 v0 = u2f(acc[j]);
            float2 v1 = u2f(acc[j+1]);
            *reinterpret_cast<ull*>(ypA + j) = f2u(v0.x, v1.x);
            *reinterpret_cast<ull*>(ypB + j) = f2u(v0.y, v1.y);
            sA += v0.x + v1.x;  qA += v0.x*v0.x + v1.x*v1.x;
            sB += v0.y + v1.y;  qB += v0.y*v0.y + v1.y*v1.y;
        }
#pragma unroll
        for (int o = 16; o; o >>= 1) {
            sA += __shfl_down_sync(0xFFFFFFFFu, sA, o);
            qA += __shfl_down_sync(0xFFFFFFFFu, qA, o);
            sB += __shfl_down_sync(0xFFFFFFFFu, sB, o);
            qB += __shfl_down_sync(0xFFFFFFFFu, qB, o);
        }
        if (lane == 0) {
            sred[0*NWARPS + wid] = sA;
            sred[1*NWARPS + wid] = qA;
            sred[2*NWARPS + wid] = sB;
            sred[3*NWARPS + wid] = qB;
        }
        __syncthreads();
        if (tid == 0) {
            float SA=0,QA=0,SB=0,QB=0;
            for (int i = 0; i < NWARPS; i++) {
                SA += sred[0*NWARPS+i]; QA += sred[1*NWARPS+i];
                SB += sred[2*NWARPS+i]; QB += sred[3*NWARPS+i];
            }
            g_part[0][c][nA]   = SA;  g_part[1][c][nA]   = QA;
            g_part[0][c][nA+1] = SB;  g_part[1][c][nA+1] = QB;
        }
        __syncthreads();   // sred reused below
    }

    // ---------------- small 5x5 conv: direct 18-wide window ----------------
    ull bcc[14];
#pragma unroll
    for (int j = 0; j < 14; j++) bcc[j] = 0ULL;

#pragma unroll
    for (int ky = 0; ky < KS; ky++) {
        // out col ox0+j needs smem col ox0 + j + kx + 13
        const ull* __restrict__ r0 = sx + (oy0 + ky + 13)*TS + ox0 + 13;
        const ull* __restrict__ wr = swS2 + ky*KS;
        ull v[18];
#pragma unroll
        for (int j = 0; j < 18; j++) v[j] = r0[j];
#pragma unroll
        for (int kx = 0; kx < KS; kx++) {
            const ull w = wr[kx];
#pragma unroll
            for (int j = 0; j < 14; j++)
                bcc[j] = f2fma(v[kx + j], w, bcc[j]);
        }
    }

    // write yS + per-block stats
    {
        float* __restrict__ ypA = g_yS + (size_t)(nA*Cc + c)*HW + oy0*Ww + ox0;
        float* __restrict__ ypB = ypA + (size_t)Cc*HW;
        float sA = 0.f, qA = 0.f, sB = 0.f, qB = 0.f;
#pragma unroll
        for (int j = 0; j < 14; j += 2) {
            float2 v0 = u2f(bcc[j]);
            float2 v1 = u2f(bcc[j+1]);
            *reinterpret_cast<ull*>(ypA + j) = f2u(v0.x, v1.x);
            *reinterpret_cast<ull*>(ypB + j) = f2u(v0.y, v1.y);
            sA += v0.x + v1.x;  qA += v0.x*v0.x + v1.x*v1.x;
            sB += v0.y + v1.y;  qB += v0.y*v0.y + v1.y*v1.y;
        }
#pragma unroll
        for (int o = 16; o; o >>= 1) {
            sA += __shfl_down_sync(0xFFFFFFFFu, sA, o);
            qA += __shfl_down_sync(0xFFFFFFFFu, qA, o);
            sB += __shfl_down_sync(0xFFFFFFFFu, sB, o);
            qB += __shfl_down_sync(0xFFFFFFFFu, qB, o);
        }
        if (lane == 0) {
            sred[0*NWARPS + wid] = sA;
            sred[1*NWARPS + wid] = qA;
            sred[2*NWARPS + wid] = sB;
            sred[3*NWARPS + wid] = qB;
        }
        __syncthreads();
        if (tid == 0) {
            float SA=0,QA=0,SB=0,QB=0;
            for (int i = 0; i < NWARPS; i++) {
                SA += sred[0*NWARPS+i]; QA += sred[1*NWARPS+i];
                SB += sred[2*NWARPS+i]; QB += sred[3*NWARPS+i];
            }
            g_part[2][c][nA]   = SA;  g_part[3][c][nA]   = QA;
            g_part[2][c][nA+1] = SB;  g_part[3][c][nA+1] = QB;
        }
    }
}

__global__ void stats_kernel(const float* __restrict__ gammaL, const float* __restrict__ betaL,
                             const float* __restrict__ gammaS, const float* __restrict__ betaS)
{
    int c = blockIdx.x*blockDim.x + threadIdx.x;
    if (c >= Cc) return;
    const float Nf = (float)(Bn*HW);
    float sL = 0.f, qL = 0.f, sS = 0.f, qS = 0.f;
#pragma unroll
    for (int n = 0; n < Bn; n++) {
        sL += g_part[0][c][n]; qL += g_part[1][c][n];
        sS += g_part[2][c][n]; qS += g_part[3][c][n];
    }
    float mL = sL / Nf, vL = qL / Nf - mL*mL;
    float invL = rsqrtf(vL + 1e-5f);
    float scL = gammaL[c] * invL;
    g_coef[0][c] = scL;
    g_coef[1][c] = betaL[c] - mL*scL;

    float mS = sS / Nf, vS = qS / Nf - mS*mS;
    float invS = rsqrtf(vS + 1e-5f);
    float scS = gammaS[c] * invS;
    g_coef[2][c] = scS;
    g_coef[3][c] = betaS[c] - mS*scS;
}

__global__ void norm_kernel(float* __restrict__ out)
{
    const int total4 = Bn*Cc*HW/4;
    int i = blockIdx.x*blockDim.x + threadIdx.x;
    if (i >= total4) return;
    const int c = (i / (HW/4)) % Cc;
    const float4 a = reinterpret_cast<const float4*>(g_yL)[i];
    const float4 b = reinterpret_cast<const float4*>(g_yS)[i];
    const float scL = g_coef[0][c], bL = g_coef[1][c];
    const float scS = g_coef[2][c], bS = g_coef[3][c];
    float4 o;
    o.x = fmaf(a.x, scL, bL) + fmaf(b.x, scS, bS);
    o.y = fmaf(a.y, scL, bL) + fmaf(b.y, scS, bS);
    o.z = fmaf(a.z, scL, bL) + fmaf(b.z, scS, bS);
    o.w = fmaf(a.w, scL, bL) + fmaf(b.w, scS, bS);
    reinterpret_cast<float4*>(out)[i] = o;
}

extern "C" void kernel_launch(void* const* d_in, const int* in_sizes, int n_in,
                              void* d_out, int out_size)
{
    const float* x       = (const float*)d_in[0];
    const float* w_large = (const float*)d_in[1];
    const float* gammaL  = (const float*)d_in[2];
    const float* betaL   = (const float*)d_in[3];
    const float* w_small = (const float*)d_in[4];
    const float* gammaS  = (const float*)d_in[5];
    const float* betaS   = (const float*)d_in[6];
    float* out = (float*)d_out;

    cudaFuncSetAttribute(conv_kernel, cudaFuncAttributeMaxDynamicSharedMemorySize, SMEM_BYTES);
    conv_kernel<<<(Bn/2)*Cc, NTHREADS, SMEM_BYTES>>>(x, w_large, w_small);
    stats_kernel<<<(Cc + 127)/128, 128>>>(gammaL, betaL, gammaS, betaS);
    const int total4 = Bn*Cc*HW/4;
    norm_kernel<<<(total4 + 255)/256, 256>>>(out);
}

// round 6
// speedup vs baseline: 1.2826x; 1.0569x over previous
#include <cuda_runtime.h>

#define Bn 16
#define Cc 384
#define Hh 56
#define Ww 56
#define HW (Hh*Ww)
#define KL 31
#define KS 5
#define PL 15
#define XT 86          // 56 + 2*15
#define TS 91          // odd stride
#define SXN 7828       // 86*91 = 7826, padded to even
#define WLN (KL*32)    // weight rows padded to 32 -> 16B-aligned pair loads
#define NTHREADS 224   // 56 rows x 4 col-groups of 14 cols; warp = 8 rows x 4 groups
#define NWARPS 7

typedef unsigned long long ull;

// Scratch (device globals: allocation-free rule)
__device__ float g_yL[(size_t)Bn*Cc*HW];
__device__ float g_yS[(size_t)Bn*Cc*HW];
__device__ float g_part[4][Cc][Bn];   // sumL, sumsqL, sumS, sumsqS
__device__ float g_coef[4][Cc];       // scaleL, biasL, scaleS, biasS

__device__ __forceinline__ ull f2fma(ull a, ull b, ull c) {
    ull d;
    asm("fma.rn.f32x2 %0, %1, %2, %3;" : "=l"(d) : "l"(a), "l"(b), "l"(c));
    return d;
}
__device__ __forceinline__ float2 u2f(ull v) {
    float2 f;
    asm("mov.b64 {%0, %1}, %2;" : "=f"(f.x), "=f"(f.y) : "l"(v));
    return f;
}
__device__ __forceinline__ ull f2u(float x, float y) {
    ull v;
    asm("mov.b64 %0, {%1, %2};" : "=l"(v) : "f"(x), "f"(y));
    return v;
}

// dynamic smem (ull units): sx[SXN], swL2[WLN], swS2[25], sred
#define SMEM_BYTES (SXN*8 + WLN*8 + 25*8 + 4*NWARPS*4)

__global__ __launch_bounds__(NTHREADS, 3)
void conv_kernel(const float* __restrict__ x,
                 const float* __restrict__ wL,
                 const float* __restrict__ wS)
{
    extern __shared__ ull dyn[];
    ull* sx   = dyn;                  // [SXN] interleaved {imgA, imgB}
    ull* swL2 = sx + SXN;             // [KL*32] {w,w}, row-padded to 32
    ull* swS2 = swL2 + WLN;           // [25] {w,w}
    float* sred = (float*)(swS2 + 25);

    const int blk = blockIdx.x;
    const int c  = blk % Cc;
    const int np = blk / Cc;
    const int nA = np*2;
    const int tid = threadIdx.x;

    // stage large weights duplicated {w,w}, padded row stride 32 (slot 31 zeroed)
    for (int i = tid; i < WLN; i += NTHREADS) {
        int ky = i >> 5, kx = i & 31;
        float w = (kx < KL) ? wL[c*KL*KL + ky*KL + kx] : 0.f;
        swL2[i] = f2u(w, w);
    }
    if (tid < KS*KS) {
        float w = wS[c*KS*KS + tid];
        swS2[tid] = f2u(w, w);
    }

    // stage both image slices interleaved, zero halo
    const float* __restrict__ xA = x + (size_t)(nA*Cc + c)*HW;
    const float* __restrict__ xB = xA + (size_t)Cc*HW;
    for (int i = tid; i < XT*TS; i += NTHREADS) {
        int r = i / TS, col = i % TS;
        int gy = r - PL, gx = col - PL;
        float a = 0.f, b = 0.f;
        if (col < XT && gy >= 0 && gy < Hh && gx >= 0 && gx < Ww) {
            a = xA[gy*Ww + gx];
            b = xB[gy*Ww + gx];
        }
        sx[i] = f2u(a, b);
    }
    __syncthreads();

    // warp-banded mapping: warp w covers rows [8w, 8w+7], 4 col-groups per row
    const int ty = tid >> 2;       // output row 0..55 (warp = 8 consecutive rows)
    const int tx = tid & 3;        // 0..3 col-group
    const int oy0 = ty, ox0 = tx*14;
    const int wid = tid >> 5, lane = tid & 31;

    // per-warp uniform ky clipping: rows [r0, r0+7]; input row gy = y+ky-15 valid in [0,55]
    const int r0 = ty & ~7;                      // warp's first row (uniform)
    const int kyLo = (8 - r0) > 0 ? (8 - r0) : 0;          // max(0, 15-(r0+7))
    const int kyHiEx = (71 - r0) < KL ? (71 - r0) : KL;    // min(31, 70-r0 + 1)

    // ---------------- large 31x31 conv: 1 row x 14 cols, packed over 2 images ----------------
    ull acc[14];
#pragma unroll
    for (int j = 0; j < 14; j++) acc[j] = 0ULL;

#pragma unroll 1
    for (int ky = kyLo; ky < kyHiEx; ky++) {
        const ull* __restrict__ r0p = sx + (oy0 + ky)*TS + ox0;
        const ulonglong2* __restrict__ wr2 =
            reinterpret_cast<const ulonglong2*>(swL2 + ky*32);

        ull win[16];
#pragma unroll
        for (int j = 0; j < 14; j++) win[j] = r0p[j];

        ulonglong2 wp = wr2[0];                 // {w0, w1}
#pragma unroll
        for (int kx = 0; kx < KL; kx += 2) {
            const ull wc0 = wp.x;
            const ull wc1 = wp.y;
            if (kx + 2 < KL) wp = wr2[(kx + 2) >> 1];   // prefetch next pair

            // body kx
#pragma unroll
            for (int j = 0; j < 14; j++)
                acc[j] = f2fma(win[(kx + j) & 15], wc0, acc[j]);
            if (kx <= 29) win[(kx + 14) & 15] = r0p[kx + 14];

            // body kx+1 (kx=30 is the last, odd partner doesn't exist)
            if (kx + 1 < KL) {
#pragma unroll
                for (int j = 0; j < 14; j++)
                    acc[j] = f2fma(win[(kx + 1 + j) & 15], wc1, acc[j]);
                if (kx + 1 <= 29) win[(kx + 15) & 15] = r0p[kx + 15];
            }
        }
    }

    // write yL (both images, packed STG.64) + per-block stats
    {
        float* __restrict__ ypA = g_yL + (size_t)(nA*Cc + c)*HW + oy0*Ww + ox0;
        float* __restrict__ ypB = ypA + (size_t)Cc*HW;
        float sA = 0.f, qA = 0.f, sB = 0.f, qB = 0.f;
#pragma unroll
        for (int j = 0; j < 14; j += 2) {
            float2 v0 = u2f(acc[j]);
            float2 v1 = u2f(acc[j+1]);
            *reinterpret_cast<ull*>(ypA + j) = f2u(v0.x, v1.x);
            *reinterpret_cast<ull*>(ypB + j) = f2u(v0.y, v1.y);
            sA += v0.x + v1.x;  qA += v0.x*v0.x + v1.x*v1.x;
            sB += v0.y + v1.y;  qB += v0.y*v0.y + v1.y*v1.y;
        }
#pragma unroll
        for (int o = 16; o; o >>= 1) {
            sA += __shfl_down_sync(0xFFFFFFFFu, sA, o);
            qA += __shfl_down_sync(0xFFFFFFFFu, qA, o);
            sB += __shfl_down_sync(0xFFFFFFFFu, sB, o);
            qB += __shfl_down_sync(0xFFFFFFFFu, qB, o);
        }
        if (lane == 0) {
            sred[0*NWARPS + wid] = sA;
            sred[1*NWARPS + wid] = qA;
            sred[2*NWARPS + wid] = sB;
            sred[3*NWARPS + wid] = qB;
        }
        __syncthreads();
        if (tid == 0) {
            float SA=0,QA=0,SB=0,QB=0;
            for (int i = 0; i < NWARPS; i++) {
                SA += sred[0*NWARPS+i]; QA += sred[1*NWARPS+i];
                SB += sred[2*NWARPS+i]; QB += sred[3*NWARPS+i];
            }
            g_part[0][c][nA]   = SA;  g_part[1][c][nA]   = QA;
            g_part[0][c][nA+1] = SB;  g_part[1][c][nA+1] = QB;
        }
        __syncthreads();   // sred reused below
    }

    // ---------------- small 5x5 conv: direct 18-wide window ----------------
    ull bcc[14];
#pragma unroll
    for (int j = 0; j < 14; j++) bcc[j] = 0ULL;

#pragma unroll
    for (int ky = 0; ky < KS; ky++) {
        // out col ox0+j needs smem col ox0 + j + kx + 13
        const ull* __restrict__ rp = sx + (oy0 + ky + 13)*TS + ox0 + 13;
        const ull* __restrict__ wr = swS2 + ky*KS;
        ull v[18];
#pragma unroll
        for (int j = 0; j < 18; j++) v[j] = rp[j];
#pragma unroll
        for (int kx = 0; kx < KS; kx++) {
            const ull w = wr[kx];
#pragma unroll
            for (int j = 0; j < 14; j++)
                bcc[j] = f2fma(v[kx + j], w, bcc[j]);
        }
    }

    // write yS + per-block stats
    {
        float* __restrict__ ypA = g_yS + (size_t)(nA*Cc + c)*HW + oy0*Ww + ox0;
        float* __restrict__ ypB = ypA + (size_t)Cc*HW;
        float sA = 0.f, qA = 0.f, sB = 0.f, qB = 0.f;
#pragma unroll
        for (int j = 0; j < 14; j += 2) {
            float2 v0 = u2f(bcc[j]);
            float2 v1 = u2f(bcc[j+1]);
            *reinterpret_cast<ull*>(ypA + j) = f2u(v0.x, v1.x);
            *reinterpret_cast<ull*>(ypB + j) = f2u(v0.y, v1.y);
            sA += v0.x + v1.x;  qA += v0.x*v0.x + v1.x*v1.x;
            sB += v0.y + v1.y;  qB += v0.y*v0.y + v1.y*v1.y;
        }
#pragma unroll
        for (int o = 16; o; o >>= 1) {
            sA += __shfl_down_sync(0xFFFFFFFFu, sA, o);
            qA += __shfl_down_sync(0xFFFFFFFFu, qA, o);
            sB += __shfl_down_sync(0xFFFFFFFFu, sB, o);
            qB += __shfl_down_sync(0xFFFFFFFFu, qB, o);
        }
        if (lane == 0) {
            sred[0*NWARPS + wid] = sA;
            sred[1*NWARPS + wid] = qA;
            sred[2*NWARPS + wid] = sB;
            sred[3*NWARPS + wid] = qB;
        }
        __syncthreads();
        if (tid == 0) {
            float SA=0,QA=0,SB=0,QB=0;
            for (int i = 0; i < NWARPS; i++) {
                SA += sred[0*NWARPS+i]; QA += sred[1*NWARPS+i];
                SB += sred[2*NWARPS+i]; QB += sred[3*NWARPS+i];
            }
            g_part[2][c][nA]   = SA;  g_part[3][c][nA]   = QA;
            g_part[2][c][nA+1] = SB;  g_part[3][c][nA+1] = QB;
        }
    }
}

__global__ void stats_kernel(const float* __restrict__ gammaL, const float* __restrict__ betaL,
                             const float* __restrict__ gammaS, const float* __restrict__ betaS)
{
    int c = blockIdx.x*blockDim.x + threadIdx.x;
    if (c >= Cc) return;
    const float Nf = (float)(Bn*HW);
    float sL = 0.f, qL = 0.f, sS = 0.f, qS = 0.f;
#pragma unroll
    for (int n = 0; n < Bn; n++) {
        sL += g_part[0][c][n]; qL += g_part[1][c][n];
        sS += g_part[2][c][n]; qS += g_part[3][c][n];
    }
    float mL = sL / Nf, vL = qL / Nf - mL*mL;
    float invL = rsqrtf(vL + 1e-5f);
    float scL = gammaL[c] * invL;
    g_coef[0][c] = scL;
    g_coef[1][c] = betaL[c] - mL*scL;

    float mS = sS / Nf, vS = qS / Nf - mS*mS;
    float invS = rsqrtf(vS + 1e-5f);
    float scS = gammaS[c] * invS;
    g_coef[2][c] = scS;
    g_coef[3][c] = betaS[c] - mS*scS;
}

__global__ void norm_kernel(float* __restrict__ out)
{
    const int total4 = Bn*Cc*HW/4;
    int i = blockIdx.x*blockDim.x + threadIdx.x;
    if (i >= total4) return;
    const int c = (i / (HW/4)) % Cc;
    const float4 a = reinterpret_cast<const float4*>(g_yL)[i];
    const float4 b = reinterpret_cast<const float4*>(g_yS)[i];
    const float scL = g_coef[0][c], bL = g_coef[1][c];
    const float scS = g_coef[2][c], bS = g_coef[3][c];
    float4 o;
    o.x = fmaf(a.x, scL, bL) + fmaf(b.x, scS, bS);
    o.y = fmaf(a.y, scL, bL) + fmaf(b.y, scS, bS);
    o.z = fmaf(a.z, scL, bL) + fmaf(b.z, scS, bS);
    o.w = fmaf(a.w, scL, bL) + fmaf(b.w, scS, bS);
    reinterpret_cast<float4*>(out)[i] = o;
}

extern "C" void kernel_launch(void* const* d_in, const int* in_sizes, int n_in,
                              void* d_out, int out_size)
{
    const float* x       = (const float*)d_in[0];
    const float* w_large = (const float*)d_in[1];
    const float* gammaL  = (const float*)d_in[2];
    const float* betaL   = (const float*)d_in[3];
    const float* w_small = (const float*)d_in[4];
    const float* gammaS  = (const float*)d_in[5];
    const float* betaS   = (const float*)d_in[6];
    float* out = (float*)d_out;

    cudaFuncSetAttribute(conv_kernel, cudaFuncAttributeMaxDynamicSharedMemorySize, SMEM_BYTES);
    conv_kernel<<<(Bn/2)*Cc, NTHREADS, SMEM_BYTES>>>(x, w_large, w_small);
    stats_kernel<<<(Cc + 127)/128, 128>>>(gammaL, betaL, gammaS, betaS);
    const int total4 = Bn*Cc*HW/4;
    norm_kernel<<<(total4 + 255)/256, 256>>>(out);
}

// round 11
// speedup vs baseline: 1.6290x; 1.2701x over previous
#include <cuda_runtime.h>
#include <cstdint>

#define Bn 16
#define Cc 384
#define Hh 56
#define Ww 56
#define HW (Hh*Ww)
#define KL 31
#define KS 5
#define NTHREADS 224   // 7 warps; warp w owns y-columns [8w, 8w+8)
#define NWARPS 7

typedef unsigned long long ull;

// ---- smem byte layout ----
#define XP_STRIDE 92                    // ull units; 92 % 16 == 12 -> conflict-free B frags
#define XP_ROWS   96
#define XP_BYTES  (XP_ROWS*XP_STRIDE*8) // 70656
#define W_OFF     XP_BYTES              // [31][32] tf32: sw[r*32+d] = w[d][r]
#define W_BYTES   (KL*32*4)             // 3968
#define SRED_OFF  (W_OFF + W_BYTES)
#define SMEM_TOTAL (SRED_OFF + 32*4)

// Scratch (device globals: allocation-free rule)
__device__ float g_yL[(size_t)Bn*Cc*HW];
__device__ float g_yS[(size_t)Bn*Cc*HW];
__device__ float g_part[4][Cc][Bn];
__device__ float g_coef[4][Cc];

__device__ __forceinline__ uint32_t tf32r(float f) {
    uint32_t u;
    asm("cvt.rna.tf32.f32 %0, %1;" : "=r"(u) : "f"(f));
    return u;
}
__device__ __forceinline__ void mma8(float* c,
                                     uint32_t a0, uint32_t a1, uint32_t a2, uint32_t a3,
                                     uint32_t b0, uint32_t b1) {
    asm volatile(
        "mma.sync.aligned.m16n8k8.row.col.f32.tf32.tf32.f32 "
        "{%0,%1,%2,%3}, {%4,%5,%6,%7}, {%8,%9}, {%0,%1,%2,%3};"
        : "+f"(c[0]), "+f"(c[1]), "+f"(c[2]), "+f"(c[3])
        : "r"(a0), "r"(a1), "r"(a2), "r"(a3), "r"(b0), "r"(b1));
}
// A-fragment value: w[d][kx] from weight column held across the warp; zero outside band
__device__ __forceinline__ uint32_t asel(float wv, int d) {
    float v = __shfl_sync(0xFFFFFFFFu, wv, d & 31);
    return ((unsigned)d < 31u) ? __float_as_uint(v) : 0u;
}

__global__ __launch_bounds__(NTHREADS, 2)
void conv_kernel(const float* __restrict__ x,
                 const float* __restrict__ wL,
                 const float* __restrict__ wS)
{
    extern __shared__ char smem[];
    ull*   xp   = (ull*)smem;                 // [96][92] packed {tf32 imgA, tf32 imgB}
    float* sw   = (float*)(smem + W_OFF);     // [31][32]: sw[r*32+d] = tf32(w[d][r])
    float* sred = (float*)(smem + SRED_OFF);

    const int blk = blockIdx.x;
    const int c   = blk % Cc;
    const int np  = blk / Cc;
    const int nA  = np * 2;
    const int tid = threadIdx.x;
    const int wid = tid >> 5, lane = tid & 31;
    const int tig = lane & 3, gid = lane >> 2;

    // stage large weights TRANSPOSED: sw[r][d] = w[d][r]  (d = band offset, r = kx loop)
    for (int i = tid; i < KL*32; i += NTHREADS) {
        int r = i >> 5, d = i & 31;
        float w = (d < KL) ? wL[c*KL*KL + d*KL + r] : 0.f;
        sw[i] = __uint_as_float(tf32r(w));
    }

    // stage padded X (both images), tf32-rounded, zero halo; rows 71..95 zero
    const float* __restrict__ xA = x + (size_t)(nA*Cc + c)*HW;
    const float* __restrict__ xB = xA + (size_t)Cc*HW;
    for (int i = tid; i < XP_ROWS*XP_STRIDE; i += NTHREADS) {
        int r = i / XP_STRIDE, col = i % XP_STRIDE;
        ull v = 0ULL;
        if (r >= 15 && r < 71 && col >= 15 && col < 71) {
            uint32_t a = tf32r(xA[(r-15)*Ww + col-15]);
            uint32_t b = tf32r(xB[(r-15)*Ww + col-15]);
            v = ((ull)b << 32) | a;
        }
        xp[i] = v;
    }
    __syncthreads();

    // ---------------- large conv: 31 banded row-GEMMs, barrier-free ----------------
    float acc[2][4][4];
#pragma unroll
    for (int im = 0; im < 2; im++)
#pragma unroll
        for (int m = 0; m < 4; m++)
#pragma unroll
            for (int r = 0; r < 4; r++) acc[im][m][r] = 0.f;

    const int y0 = wid * 8;

#pragma unroll 1
    for (int kx = 0; kx < KL; kx++) {
        const float wv = sw[kx*32 + lane];             // lane d holds w[d][kx]
        const ull* __restrict__ bcol = xp + (y0 + kx + gid);

        // hoist the 12 distinct B row-chunks (u0 = 8*ch), rows {tig, tig+4}
        ull br[12][2];
#pragma unroll
        for (int ch = 0; ch < 12; ch++) {
            br[ch][0] = bcol[(size_t)(8*ch + tig)     * XP_STRIDE];
            br[ch][1] = bcol[(size_t)(8*ch + tig + 4) * XP_STRIDE];
        }

#pragma unroll
        for (int cc = 0; cc < 6; cc++) {
            const int d0 = cc*8 + tig - gid;
            const uint32_t a0 = asel(wv, d0);
            const uint32_t a1 = asel(wv, d0 - 8);
            const uint32_t a2 = asel(wv, d0 + 4);
            const uint32_t a3 = asel(wv, d0 - 4);
#pragma unroll
            for (int m = 0; m < 4; m++) {
                const int ch = 2*m + cc;
                const uint2 e0 = *(const uint2*)&br[ch][0];
                const uint2 e1 = *(const uint2*)&br[ch][1];
                mma8(acc[0][m], a0, a1, a2, a3, e0.x, e1.x);
                mma8(acc[1][m], a0, a1, a2, a3, e0.y, e1.y);
            }
        }
    }

    // epilogue: D[x = 16m+gid(+8)][y = y0+2tig+{0,1}] -> g_yL + stats
    {
        float s0 = 0.f, q0 = 0.f, s1 = 0.f, q1 = 0.f;
#pragma unroll
        for (int im = 0; im < 2; im++) {
            float* __restrict__ yp = g_yL + (size_t)((nA+im)*Cc + c)*HW;
            float s = 0.f, q = 0.f;
#pragma unroll
            for (int m = 0; m < 4; m++) {
                const int x0 = m*16 + gid;
                const int yy = y0 + 2*tig;
                const float v0 = acc[im][m][0], v1 = acc[im][m][1];
                *(float2*)(yp + x0*Ww + yy) = make_float2(v0, v1);
                s += v0 + v1; q += v0*v0 + v1*v1;
                if (m < 3) {
                    const float v2 = acc[im][m][2], v3 = acc[im][m][3];
                    *(float2*)(yp + (x0+8)*Ww + yy) = make_float2(v2, v3);
                    s += v2 + v3; q += v2*v2 + v3*v3;
                }
            }
            if (im == 0) { s0 = s; q0 = q; } else { s1 = s; q1 = q; }
        }
#pragma unroll
        for (int o = 16; o; o >>= 1) {
            s0 += __shfl_down_sync(0xFFFFFFFFu, s0, o);
            q0 += __shfl_down_sync(0xFFFFFFFFu, q0, o);
            s1 += __shfl_down_sync(0xFFFFFFFFu, s1, o);
            q1 += __shfl_down_sync(0xFFFFFFFFu, q1, o);
        }
        if (lane == 0) {
            sred[0*NWARPS + wid] = s0;
            sred[1*NWARPS + wid] = q0;
            sred[2*NWARPS + wid] = s1;
            sred[3*NWARPS + wid] = q1;
        }
        __syncthreads();
        if (tid == 0) {
            float S0=0,Q0=0,S1=0,Q1=0;
            for (int i = 0; i < NWARPS; i++) {
                S0 += sred[0*NWARPS+i]; Q0 += sred[1*NWARPS+i];
                S1 += sred[2*NWARPS+i]; Q1 += sred[3*NWARPS+i];
            }
            g_part[0][c][nA]   = S0;  g_part[1][c][nA]   = Q0;
            g_part[0][c][nA+1] = S1;  g_part[1][c][nA+1] = Q1;
        }
        __syncthreads();   // sred reused below
    }

    // ---------------- small 5x5 conv: fp32 from gmem (L1-resident), both images ----------------
    {
        float ws[KS*KS];
#pragma unroll
        for (int i = 0; i < KS*KS; i++) ws[i] = wS[c*KS*KS + i];

        float* __restrict__ ypA = g_yS + (size_t)(nA*Cc + c)*HW;
        float* __restrict__ ypB = ypA + (size_t)Cc*HW;
        float s0 = 0.f, q0 = 0.f, s1 = 0.f, q1 = 0.f;
#pragma unroll 1
        for (int p = tid; p < HW; p += NTHREADS) {
            const int oy = p / Ww, ox = p % Ww;
            float aA = 0.f, aB = 0.f;
#pragma unroll
            for (int ky = 0; ky < KS; ky++) {
                const int gy = oy + ky - 2;
                if (gy < 0 || gy >= Hh) continue;
#pragma unroll
                for (int kx = 0; kx < KS; kx++) {
                    const int gx = ox + kx - 2;
                    if (gx < 0 || gx >= Ww) continue;
                    const float w = ws[ky*KS + kx];
                    aA = fmaf(xA[gy*Ww + gx], w, aA);
                    aB = fmaf(xB[gy*Ww + gx], w, aB);
                }
            }
            ypA[p] = aA;  ypB[p] = aB;
            s0 += aA; q0 += aA*aA;
            s1 += aB; q1 += aB*aB;
        }
#pragma unroll
        for (int o = 16; o; o >>= 1) {
            s0 += __shfl_down_sync(0xFFFFFFFFu, s0, o);
            q0 += __shfl_down_sync(0xFFFFFFFFu, q0, o);
            s1 += __shfl_down_sync(0xFFFFFFFFu, s1, o);
            q1 += __shfl_down_sync(0xFFFFFFFFu, q1, o);
        }
        if (lane == 0) {
            sred[0*NWARPS + wid] = s0;
            sred[1*NWARPS + wid] = q0;
            sred[2*NWARPS + wid] = s1;
            sred[3*NWARPS + wid] = q1;
        }
        __syncthreads();
        if (tid == 0) {
            float S0=0,Q0=0,S1=0,Q1=0;
            for (int i = 0; i < NWARPS; i++) {
                S0 += sred[0*NWARPS+i]; Q0 += sred[1*NWARPS+i];
                S1 += sred[2*NWARPS+i]; Q1 += sred[3*NWARPS+i];
            }
            g_part[2][c][nA]   = S0;  g_part[3][c][nA]   = Q0;
            g_part[2][c][nA+1] = S1;  g_part[3][c][nA+1] = Q1;
        }
    }
}

__global__ void stats_kernel(const float* __restrict__ gammaL, const float* __restrict__ betaL,
                             const float* __restrict__ gammaS, const float* __restrict__ betaS)
{
    int c = blockIdx.x*blockDim.x + threadIdx.x;
    if (c >= Cc) return;
    const float Nf = (float)(Bn*HW);
    float sL = 0.f, qL = 0.f, sS = 0.f, qS = 0.f;
#pragma unroll
    for (int n = 0; n < Bn; n++) {
        sL += g_part[0][c][n]; qL += g_part[1][c][n];
        sS += g_part[2][c][n]; qS += g_part[3][c][n];
    }
    float mL = sL / Nf, vL = qL / Nf - mL*mL;
    float invL = rsqrtf(vL + 1e-5f);
    float scL = gammaL[c] * invL;
    g_coef[0][c] = scL;
    g_coef[1][c] = betaL[c] - mL*scL;

    float mS = sS / Nf, vS = qS / Nf - mS*mS;
    float invS = rsqrtf(vS + 1e-5f);
    float scS = gammaS[c] * invS;
    g_coef[2][c] = scS;
    g_coef[3][c] = betaS[c] - mS*scS;
}

__global__ void norm_kernel(float* __restrict__ out)
{
    const int total4 = Bn*Cc*HW/4;
    int i = blockIdx.x*blockDim.x + threadIdx.x;
    if (i >= total4) return;
    const int c = (i / (HW/4)) % Cc;
    const float4 a = reinterpret_cast<const float4*>(g_yL)[i];
    const float4 b = reinterpret_cast<const float4*>(g_yS)[i];
    const float scL = g_coef[0][c], bL = g_coef[1][c];
    const float scS = g_coef[2][c], bS = g_coef[3][c];
    float4 o;
    o.x = fmaf(a.x, scL, bL) + fmaf(b.x, scS, bS);
    o.y = fmaf(a.y, scL, bL) + fmaf(b.y, scS, bS);
    o.z = fmaf(a.z, scL, bL) + fmaf(b.z, scS, bS);
    o.w = fmaf(a.w, scL, bL) + fmaf(b.w, scS, bS);
    reinterpret_cast<float4*>(out)[i] = o;
}

extern "C" void kernel_launch(void* const* d_in, const int* in_sizes, int n_in,
                              void* d_out, int out_size)
{
    const float* x       = (const float*)d_in[0];
    const float* w_large = (const float*)d_in[1];
    const float* gammaL  = (const float*)d_in[2];
    const float* betaL   = (const float*)d_in[3];
    const float* w_small = (const float*)d_in[4];
    const float* gammaS  = (const float*)d_in[5];
    const float* betaS   = (const float*)d_in[6];
    float* out = (float*)d_out;

    cudaFuncSetAttribute(conv_kernel, cudaFuncAttributeMaxDynamicSharedMemorySize, SMEM_TOTAL);
    conv_kernel<<<(Bn/2)*Cc, NTHREADS, SMEM_TOTAL>>>(x, w_large, w_small);
    stats_kernel<<<(Cc + 127)/128, 128>>>(gammaL, betaL, gammaS, betaS);
    const int total4 = Bn*Cc*HW/4;
    norm_kernel<<<(total4 + 255)/256, 256>>>(out);
}

// round 13
// speedup vs baseline: 1.9132x; 1.1745x over previous
#include <cuda_runtime.h>
#include <cstdint>

#define Bn 16
#define Cc 384
#define Hh 56
#define Ww 56
#define HW (Hh*Ww)
#define KL 31
#define KS 5
#define NTHREADS 448   // 14 warps: wy = wid%7 owns y-cols [8wy,8wy+8), im = wid/7
#define NWARPS 14

typedef unsigned long long ull;

// ---- smem byte layout ----
#define XP_STRIDE 92                    // ull units
#define XP_ROWS   96
#define XP_BYTES  (XP_ROWS*XP_STRIDE*8) // 70656
#define W_OFF     XP_BYTES              // [31][32] tf32: sw[r*32+d] = w[d][r]
#define W_BYTES   (KL*32*4)
#define SRED_OFF  (W_OFF + W_BYTES)
#define SMEM_TOTAL (SRED_OFF + 64*4)

// Scratch (device globals: allocation-free rule)
__device__ float g_yL[(size_t)Bn*Cc*HW];
__device__ float g_yS[(size_t)Bn*Cc*HW];
__device__ float g_part[4][Cc][Bn];
__device__ float g_coef[4][Cc];

__device__ __forceinline__ uint32_t tf32r(float f) {
    uint32_t u;
    asm("cvt.rna.tf32.f32 %0, %1;" : "=r"(u) : "f"(f));
    return u;
}
__device__ __forceinline__ void mma8(float* c,
                                     uint32_t a0, uint32_t a1, uint32_t a2, uint32_t a3,
                                     uint32_t b0, uint32_t b1) {
    asm volatile(
        "mma.sync.aligned.m16n8k8.row.col.f32.tf32.tf32.f32 "
        "{%0,%1,%2,%3}, {%4,%5,%6,%7}, {%8,%9}, {%0,%1,%2,%3};"
        : "+f"(c[0]), "+f"(c[1]), "+f"(c[2]), "+f"(c[3])
        : "r"(a0), "r"(a1), "r"(a2), "r"(a3), "r"(b0), "r"(b1));
}
// A-fragment value: w[d][kx] from weight column held across the warp; zero outside band
__device__ __forceinline__ uint32_t asel(float wv, int d) {
    float v = __shfl_sync(0xFFFFFFFFu, wv, d & 31);
    return ((unsigned)d < 31u) ? __float_as_uint(v) : 0u;
}

__global__ __launch_bounds__(NTHREADS, 2)
void conv_kernel(const float* __restrict__ x,
                 const float* __restrict__ wL,
                 const float* __restrict__ wS)
{
    extern __shared__ char smem[];
    ull*   xp   = (ull*)smem;                 // [96][92] packed {tf32 imgA, tf32 imgB}
    float* sw   = (float*)(smem + W_OFF);     // [31][32]: sw[r*32+d] = tf32(w[d][r])
    float* sred = (float*)(smem + SRED_OFF);

    const int blk = blockIdx.x;
    const int c   = blk % Cc;
    const int np  = blk / Cc;
    const int nA  = np * 2;
    const int tid = threadIdx.x;
    const int wid = tid >> 5, lane = tid & 31;
    const int tig = lane & 3, gid = lane >> 2;
    const int wy  = (wid < 7) ? wid : wid - 7;   // y-block
    const int im  = (wid < 7) ? 0 : 1;           // image owned by this warp

    // stage large weights TRANSPOSED: sw[r][d] = w[d][r]
    for (int i = tid; i < KL*32; i += NTHREADS) {
        int r = i >> 5, d = i & 31;
        float w = (d < KL) ? wL[c*KL*KL + d*KL + r] : 0.f;
        sw[i] = __uint_as_float(tf32r(w));
    }

    // stage padded X (both images), tf32-rounded, zero halo; rows 71..95 zero
    const float* __restrict__ xA = x + (size_t)(nA*Cc + c)*HW;
    const float* __restrict__ xB = xA + (size_t)Cc*HW;
    for (int i = tid; i < XP_ROWS*XP_STRIDE; i += NTHREADS) {
        int r = i / XP_STRIDE, col = i % XP_STRIDE;
        ull v = 0ULL;
        if (r >= 15 && r < 71 && col >= 15 && col < 71) {
            uint32_t a = tf32r(xA[(r-15)*Ww + col-15]);
            uint32_t b = tf32r(xB[(r-15)*Ww + col-15]);
            v = ((ull)b << 32) | a;
        }
        xp[i] = v;
    }
    __syncthreads();

    // ---------------- large conv: 31 banded row-GEMMs, barrier-free ----------------
    float acc[4][4];
#pragma unroll
    for (int m = 0; m < 4; m++)
#pragma unroll
        for (int r = 0; r < 4; r++) acc[m][r] = 0.f;

    const int y0 = wy * 8;
    const uint32_t* __restrict__ bw = (const uint32_t*)xp;

#pragma unroll 1
    for (int kx = 0; kx < KL; kx++) {
        const float wv = sw[kx*32 + lane];             // lane d holds w[d][kx]
        const int base = (y0 + kx + gid)*2 + im;

        // hoist 12 B row-chunk fragments for this image only (LDS.32 halves)
        uint32_t br[12][2];
#pragma unroll
        for (int ch = 0; ch < 12; ch++) {
            br[ch][0] = bw[(size_t)(8*ch + tig)     * (XP_STRIDE*2) + base];
            br[ch][1] = bw[(size_t)(8*ch + tig + 4) * (XP_STRIDE*2) + base];
        }

        // shfl-reuse A fragments: a1(cc) = a0(cc-1), a3(cc) = a2(cc-1)
        uint32_t a0m = asel(wv, tig - gid - 8);
        uint32_t a2m = asel(wv, tig - gid - 4);
#pragma unroll
        for (int cc = 0; cc < 6; cc++) {
            const int d0 = cc*8 + tig - gid;
            const uint32_t a0 = asel(wv, d0);
            const uint32_t a2 = asel(wv, d0 + 4);
#pragma unroll
            for (int m = 0; m < 4; m++) {
                const int ch = 2*m + cc;
                mma8(acc[m], a0, a0m, a2, a2m, br[ch][0], br[ch][1]);
            }
            a0m = a0;
            a2m = a2;
        }
    }

    // epilogue: D[x = 16m+gid(+8)][y = y0+2tig+{0,1}] -> g_yL + stats (one image per warp)
    {
        float* __restrict__ yp = g_yL + (size_t)((nA+im)*Cc + c)*HW;
        float s = 0.f, q = 0.f;
#pragma unroll
        for (int m = 0; m < 4; m++) {
            const int x0 = m*16 + gid;
            const int yy = y0 + 2*tig;
            const float v0 = acc[m][0], v1 = acc[m][1];
            *(float2*)(yp + x0*Ww + yy) = make_float2(v0, v1);
            s += v0 + v1; q += v0*v0 + v1*v1;
            if (m < 3) {
                const float v2 = acc[m][2], v3 = acc[m][3];
                *(float2*)(yp + (x0+8)*Ww + yy) = make_float2(v2, v3);
                s += v2 + v3; q += v2*v2 + v3*v3;
            }
        }
#pragma unroll
        for (int o = 16; o; o >>= 1) {
            s += __shfl_down_sync(0xFFFFFFFFu, s, o);
            q += __shfl_down_sync(0xFFFFFFFFu, q, o);
        }
        if (lane == 0) { sred[wid] = s; sred[NWARPS + wid] = q; }
        __syncthreads();
        if (tid == 0) {
            float S0=0,Q0=0,S1=0,Q1=0;
            for (int i = 0; i < 7; i++) {
                S0 += sred[i];      Q0 += sred[NWARPS + i];
                S1 += sred[7 + i];  Q1 += sred[NWARPS + 7 + i];
            }
            g_part[0][c][nA]   = S0;  g_part[1][c][nA]   = Q0;
            g_part[0][c][nA+1] = S1;  g_part[1][c][nA+1] = Q1;
        }
        __syncthreads();   // sred reused below
    }

    // ---------------- small 5x5 conv: fp32 from gmem (L1-resident), both images ----------------
    {
        float ws[KS*KS];
#pragma unroll
        for (int i = 0; i < KS*KS; i++) ws[i] = wS[c*KS*KS + i];

        float* __restrict__ ypA = g_yS + (size_t)(nA*Cc + c)*HW;
        float* __restrict__ ypB = ypA + (size_t)Cc*HW;
        float s0 = 0.f, q0 = 0.f, s1 = 0.f, q1 = 0.f;
#pragma unroll 1
        for (int p = tid; p < HW; p += NTHREADS) {
            const int oy = p / Ww, ox = p % Ww;
            float aA = 0.f, aB = 0.f;
#pragma unroll
            for (int ky = 0; ky < KS; ky++) {
                const int gy = oy + ky - 2;
                if (gy < 0 || gy >= Hh) continue;
#pragma unroll
                for (int kx = 0; kx < KS; kx++) {
                    const int gx = ox + kx - 2;
                    if (gx < 0 || gx >= Ww) continue;
                    const float w = ws[ky*KS + kx];
                    aA = fmaf(xA[gy*Ww + gx], w, aA);
                    aB = fmaf(xB[gy*Ww + gx], w, aB);
                }
            }
            ypA[p] = aA;  ypB[p] = aB;
            s0 += aA; q0 += aA*aA;
            s1 += aB; q1 += aB*aB;
        }
#pragma unroll
        for (int o = 16; o; o >>= 1) {
            s0 += __shfl_down_sync(0xFFFFFFFFu, s0, o);
            q0 += __shfl_down_sync(0xFFFFFFFFu, q0, o);
            s1 += __shfl_down_sync(0xFFFFFFFFu, s1, o);
            q1 += __shfl_down_sync(0xFFFFFFFFu, q1, o);
        }
        if (lane == 0) {
            sred[0*NWARPS + wid] = s0;
            sred[1*NWARPS + wid] = q0;
            sred[2*NWARPS + wid] = s1;
            sred[3*NWARPS + wid] = q1;
        }
        __syncthreads();
        if (tid == 0) {
            float S0=0,Q0=0,S1=0,Q1=0;
            for (int i = 0; i < NWARPS; i++) {
                S0 += sred[0*NWARPS+i]; Q0 += sred[1*NWARPS+i];
                S1 += sred[2*NWARPS+i]; Q1 += sred[3*NWARPS+i];
            }
            g_part[2][c][nA]   = S0;  g_part[3][c][nA]   = Q0;
            g_part[2][c][nA+1] = S1;  g_part[3][c][nA+1] = Q1;
        }
    }
}

__global__ void stats_kernel(const float* __restrict__ gammaL, const float* __restrict__ betaL,
                             const float* __restrict__ gammaS, const float* __restrict__ betaS)
{
    int c = blockIdx.x*blockDim.x + threadIdx.x;
    if (c >= Cc) return;
    const float Nf = (float)(Bn*HW);
    float sL = 0.f, qL = 0.f, sS = 0.f, qS = 0.f;
#pragma unroll
    for (int n = 0; n < Bn; n++) {
        sL += g_part[0][c][n]; qL += g_part[1][c][n];
        sS += g_part[2][c][n]; qS += g_part[3][c][n];
    }
    float mL = sL / Nf, vL = qL / Nf - mL*mL;
    float invL = rsqrtf(vL + 1e-5f);
    float scL = gammaL[c] * invL;
    g_coef[0][c] = scL;
    g_coef[1][c] = betaL[c] - mL*scL;

    float mS = sS / Nf, vS = qS / Nf - mS*mS;
    float invS = rsqrtf(vS + 1e-5f);
    float scS = gammaS[c] * invS;
    g_coef[2][c] = scS;
    g_coef[3][c] = betaS[c] - mS*scS;
}

__global__ void norm_kernel(float* __restrict__ out)
{
    const int total4 = Bn*Cc*HW/4;
    int i = blockIdx.x*blockDim.x + threadIdx.x;
    if (i >= total4) return;
    const int c = (i / (HW/4)) % Cc;
    const float4 a = reinterpret_cast<const float4*>(g_yL)[i];
    const float4 b = reinterpret_cast<const float4*>(g_yS)[i];
    const float scL = g_coef[0][c], bL = g_coef[1][c];
    const float scS = g_coef[2][c], bS = g_coef[3][c];
    float4 o;
    o.x = fmaf(a.x, scL, bL) + fmaf(b.x, scS, bS);
    o.y = fmaf(a.y, scL, bL) + fmaf(b.y, scS, bS);
    o.z = fmaf(a.z, scL, bL) + fmaf(b.z, scS, bS);
    o.w = fmaf(a.w, scL, bL) + fmaf(b.w, scS, bS);
    reinterpret_cast<float4*>(out)[i] = o;
}

extern "C" void kernel_launch(void* const* d_in, const int* in_sizes, int n_in,
                              void* d_out, int out_size)
{
    const float* x       = (const float*)d_in[0];
    const float* w_large = (const float*)d_in[1];
    const float* gammaL  = (const float*)d_in[2];
    const float* betaL   = (const float*)d_in[3];
    const float* w_small = (const float*)d_in[4];
    const float* gammaS  = (const float*)d_in[5];
    const float* betaS   = (const float*)d_in[6];
    float* out = (float*)d_out;

    cudaFuncSetAttribute(conv_kernel, cudaFuncAttributeMaxDynamicSharedMemorySize, SMEM_TOTAL);
    conv_kernel<<<(Bn/2)*Cc, NTHREADS, SMEM_TOTAL>>>(x, w_large, w_small);
    stats_kernel<<<(Cc + 127)/128, 128>>>(gammaL, betaL, gammaS, betaS);
    const int total4 = Bn*Cc*HW/4;
    norm_kernel<<<(total4 + 255)/256, 256>>>(out);
}

// round 16
// speedup vs baseline: 1.9721x; 1.0308x over previous
#include <cuda_runtime.h>
#include <cstdint>

#define Bn 16
#define Cc 384
#define Hh 56
#define Ww 56
#define HW (Hh*Ww)
#define KL 31
#define KS 5
#define NTHREADS 448   // 14 warps: wy = wid%7 owns y-cols [8wy,8wy+8), im = wid/7
#define NWARPS 14

typedef unsigned long long ull;

// ---- smem byte layout ----
#define XP_STRIDE 92                    // ull units
#define XP_ROWS   96
#define XP_BYTES  (XP_ROWS*XP_STRIDE*8) // 70656
#define WP_OFF    XP_BYTES              // padded weight table [64][33] floats: row d+16 = w[d][*]
#define WP_ROWS   64
#define WP_STRIDE 33
#define WP_BYTES  (WP_ROWS*WP_STRIDE*4) // 8448
#define SRED_OFF  (WP_OFF + WP_BYTES)
#define SMEM_TOTAL (SRED_OFF + 64*4)

// Scratch (device globals: allocation-free rule)
__device__ float g_yL[(size_t)Bn*Cc*HW];
__device__ float g_yS[(size_t)Bn*Cc*HW];
__device__ float g_part[4][Cc][Bn];
__device__ float g_coef[4][Cc];

__device__ __forceinline__ uint32_t tf32r(float f) {
    uint32_t u;
    asm("cvt.rna.tf32.f32 %0, %1;" : "=r"(u) : "f"(f));
    return u;
}
__device__ __forceinline__ void mma8(float* c,
                                     uint32_t a0, uint32_t a1, uint32_t a2, uint32_t a3,
                                     uint32_t b0, uint32_t b1) {
    asm volatile(
        "mma.sync.aligned.m16n8k8.row.col.f32.tf32.tf32.f32 "
        "{%0,%1,%2,%3}, {%4,%5,%6,%7}, {%8,%9}, {%0,%1,%2,%3};"
        : "+f"(c[0]), "+f"(c[1]), "+f"(c[2]), "+f"(c[3])
        : "r"(a0), "r"(a1), "r"(a2), "r"(a3), "r"(b0), "r"(b1));
}

__global__ __launch_bounds__(NTHREADS, 2)
void conv_kernel(const float* __restrict__ x,
                 const float* __restrict__ wL,
                 const float* __restrict__ wS)
{
    extern __shared__ char smem[];
    ull*   xp   = (ull*)smem;                 // [96][92] packed {tf32 imgA, tf32 imgB}
    float* swp  = (float*)(smem + WP_OFF);    // [64][33]: swp[d+16][kx] = tf32(w[d][kx]), zero pad
    float* sred = (float*)(smem + SRED_OFF);

    const int blk = blockIdx.x;
    const int c   = blk % Cc;
    const int np  = blk / Cc;
    const int nA  = np * 2;
    const int tid = threadIdx.x;
    const int wid = tid >> 5, lane = tid & 31;
    const int tig = lane & 3, gid = lane >> 2;
    const int wy  = (wid < 7) ? wid : wid - 7;   // y-block
    const int im  = (wid < 7) ? 0 : 1;           // image owned by this warp

    // zero-init padded weight table, then fill rows d = 0..30 (at row index d+16)
    for (int i = tid; i < WP_ROWS*WP_STRIDE; i += NTHREADS) swp[i] = 0.f;
    __syncthreads();
    for (int i = tid; i < KL*KL; i += NTHREADS) {
        int d = i / KL, kx = i % KL;
        swp[(d + 16)*WP_STRIDE + kx] = __uint_as_float(tf32r(wL[c*KL*KL + d*KL + kx]));
    }

    // stage padded X (both images), tf32-rounded, zero halo; rows 71..95 zero
    const float* __restrict__ xA = x + (size_t)(nA*Cc + c)*HW;
    const float* __restrict__ xB = xA + (size_t)Cc*HW;
    for (int i = tid; i < XP_ROWS*XP_STRIDE; i += NTHREADS) {
        int r = i / XP_STRIDE, col = i % XP_STRIDE;
        ull v = 0ULL;
        if (r >= 15 && r < 71 && col >= 15 && col < 71) {
            uint32_t a = tf32r(xA[(r-15)*Ww + col-15]);
            uint32_t b = tf32r(xB[(r-15)*Ww + col-15]);
            v = ((ull)b << 32) | a;
        }
        xp[i] = v;
    }
    __syncthreads();

    // ---------------- large conv: 31 banded row-GEMMs, barrier-free ----------------
    float acc[4][4];
#pragma unroll
    for (int m = 0; m < 4; m++)
#pragma unroll
        for (int r = 0; r < 4; r++) acc[m][r] = 0.f;

    const int y0 = wy * 8;
    const uint32_t* __restrict__ bw = (const uint32_t*)xp;

    // per-lane A-row pointers: wrow[i]   = row of a0 for cc = i-1  (d = (i-1)*8 + tig - gid)
    //                          wrow[7+i] = row of a2 for cc = i-1  (d + 4)
    const float* wrow[14];
#pragma unroll
    for (int i = 0; i < 7; i++) {
        const int d0 = (i - 1)*8 + tig - gid;
        wrow[i]     = swp + (d0 + 16)*WP_STRIDE;
        wrow[7 + i] = swp + (d0 + 20)*WP_STRIDE;
    }

#pragma unroll 1
    for (int kx = 0; kx < KL; kx++) {
        const int base = (y0 + kx + gid)*2 + im;

        // A fragments: 14 direct LDS.32 (broadcast/conflict-free), no shfl, no selp
        uint32_t a0[7], a2[7];
#pragma unroll
        for (int i = 0; i < 7; i++) {
            a0[i] = __float_as_uint(wrow[i][kx]);
            a2[i] = __float_as_uint(wrow[7 + i][kx]);
        }

        // hoist 12 B row-chunk fragments for this image only (LDS.32 halves)
        uint32_t br[12][2];
#pragma unroll
        for (int ch = 0; ch < 12; ch++) {
            br[ch][0] = bw[(size_t)(8*ch + tig)     * (XP_STRIDE*2) + base];
            br[ch][1] = bw[(size_t)(8*ch + tig + 4) * (XP_STRIDE*2) + base];
        }

#pragma unroll
        for (int cc = 0; cc < 6; cc++) {
#pragma unroll
            for (int m = 0; m < 4; m++) {
                const int ch = 2*m + cc;
                mma8(acc[m], a0[cc+1], a0[cc], a2[cc+1], a2[cc], br[ch][0], br[ch][1]);
            }
        }
    }

    // epilogue: D[x = 16m+gid(+8)][y = y0+2tig+{0,1}] -> g_yL + stats (one image per warp)
    {
        float* __restrict__ yp = g_yL + (size_t)((nA+im)*Cc + c)*HW;
        float s = 0.f, q = 0.f;
#pragma unroll
        for (int m = 0; m < 4; m++) {
            const int x0 = m*16 + gid;
            const int yy = y0 + 2*tig;
            const float v0 = acc[m][0], v1 = acc[m][1];
            *(float2*)(yp + x0*Ww + yy) = make_float2(v0, v1);
            s += v0 + v1; q += v0*v0 + v1*v1;
            if (m < 3) {
                const float v2 = acc[m][2], v3 = acc[m][3];
                *(float2*)(yp + (x0+8)*Ww + yy) = make_float2(v2, v3);
                s += v2 + v3; q += v2*v2 + v3*v3;
            }
        }
#pragma unroll
        for (int o = 16; o; o >>= 1) {
            s += __shfl_down_sync(0xFFFFFFFFu, s, o);
            q += __shfl_down_sync(0xFFFFFFFFu, q, o);
        }
        if (lane == 0) { sred[wid] = s; sred[NWARPS + wid] = q; }
        __syncthreads();
        if (tid == 0) {
            float S0=0,Q0=0,S1=0,Q1=0;
            for (int i = 0; i < 7; i++) {
                S0 += sred[i];      Q0 += sred[NWARPS + i];
                S1 += sred[7 + i];  Q1 += sred[NWARPS + 7 + i];
            }
            g_part[0][c][nA]   = S0;  g_part[1][c][nA]   = Q0;
            g_part[0][c][nA+1] = S1;  g_part[1][c][nA+1] = Q1;
        }
        __syncthreads();   // sred reused below
    }

    // ---------------- small 5x5 conv: fp32 from gmem (L1-resident), both images ----------------
    {
        float ws[KS*KS];
#pragma unroll
        for (int i = 0; i < KS*KS; i++) ws[i] = wS[c*KS*KS + i];

        float* __restrict__ ypA = g_yS + (size_t)(nA*Cc + c)*HW;
        float* __restrict__ ypB = ypA + (size_t)Cc*HW;
        float s0 = 0.f, q0 = 0.f, s1 = 0.f, q1 = 0.f;
#pragma unroll 1
        for (int p = tid; p < HW; p += NTHREADS) {
            const int oy = p / Ww, ox = p % Ww;
            float aA = 0.f, aB = 0.f;
#pragma unroll
            for (int ky = 0; ky < KS; ky++) {
                const int gy = oy + ky - 2;
                if (gy < 0 || gy >= Hh) continue;
#pragma unroll
                for (int kx = 0; kx < KS; kx++) {
                    const int gx = ox + kx - 2;
                    if (gx < 0 || gx >= Ww) continue;
                    const float w = ws[ky*KS + kx];
                    aA = fmaf(xA[gy*Ww + gx], w, aA);
                    aB = fmaf(xB[gy*Ww + gx], w, aB);
                }
            }
            ypA[p] = aA;  ypB[p] = aB;
            s0 += aA; q0 += aA*aA;
            s1 += aB; q1 += aB*aB;
        }
#pragma unroll
        for (int o = 16; o; o >>= 1) {
            s0 += __shfl_down_sync(0xFFFFFFFFu, s0, o);
            q0 += __shfl_down_sync(0xFFFFFFFFu, q0, o);
            s1 += __shfl_down_sync(0xFFFFFFFFu, s1, o);
            q1 += __shfl_down_sync(0xFFFFFFFFu, q1, o);
        }
        if (lane == 0) {
            sred[0*NWARPS + wid] = s0;
            sred[1*NWARPS + wid] = q0;
            sred[2*NWARPS + wid] = s1;
            sred[3*NWARPS + wid] = q1;
        }
        __syncthreads();
        if (tid == 0) {
            float S0=0,Q0=0,S1=0,Q1=0;
            for (int i = 0; i < NWARPS; i++) {
                S0 += sred[0*NWARPS+i]; Q0 += sred[1*NWARPS+i];
                S1 += sred[2*NWARPS+i]; Q1 += sred[3*NWARPS+i];
            }
            g_part[2][c][nA]   = S0;  g_part[3][c][nA]   = Q0;
            g_part[2][c][nA+1] = S1;  g_part[3][c][nA+1] = Q1;
        }
    }
}

__global__ void stats_kernel(const float* __restrict__ gammaL, const float* __restrict__ betaL,
                             const float* __restrict__ gammaS, const float* __restrict__ betaS)
{
    int c = blockIdx.x*blockDim.x + threadIdx.x;
    if (c >= Cc) return;
    const float Nf = (float)(Bn*HW);
    float sL = 0.f, qL = 0.f, sS = 0.f, qS = 0.f;
#pragma unroll
    for (int n = 0; n < Bn; n++) {
        sL += g_part[0][c][n]; qL += g_part[1][c][n];
        sS += g_part[2][c][n]; qS += g_part[3][c][n];
    }
    float mL = sL / Nf, vL = qL / Nf - mL*mL;
    float invL = rsqrtf(vL + 1e-5f);
    float scL = gammaL[c] * invL;
    g_coef[0][c] = scL;
    g_coef[1][c] = betaL[c] - mL*scL;

    float mS = sS / Nf, vS = qS / Nf - mS*mS;
    float invS = rsqrtf(vS + 1e-5f);
    float scS = gammaS[c] * invS;
    g_coef[2][c] = scS;
    g_coef[3][c] = betaS[c] - mS*scS;
}

__global__ void norm_kernel(float* __restrict__ out)
{
    const int total4 = Bn*Cc*HW/4;
    int i = blockIdx.x*blockDim.x + threadIdx.x;
    if (i >= total4) return;
    const int c = (i / (HW/4)) % Cc;
    const float4 a = reinterpret_cast<const float4*>(g_yL)[i];
    const float4 b = reinterpret_cast<const float4*>(g_yS)[i];
    const float scL = g_coef[0][c], bL = g_coef[1][c];
    const float scS = g_coef[2][c], bS = g_coef[3][c];
    float4 o;
    o.x = fmaf(a.x, scL, bL) + fmaf(b.x, scS, bS);
    o.y = fmaf(a.y, scL, bL) + fmaf(b.y, scS, bS);
    o.z = fmaf(a.z, scL, bL) + fmaf(b.z, scS, bS);
    o.w = fmaf(a.w, scL, bL) + fmaf(b.w, scS, bS);
    reinterpret_cast<float4*>(out)[i] = o;
}

extern "C" void kernel_launch(void* const* d_in, const int* in_sizes, int n_in,
                              void* d_out, int out_size)
{
    const float* x       = (const float*)d_in[0];
    const float* w_large = (const float*)d_in[1];
    const float* gammaL  = (const float*)d_in[2];
    const float* betaL   = (const float*)d_in[3];
    const float* w_small = (const float*)d_in[4];
    const float* gammaS  = (const float*)d_in[5];
    const float* betaS   = (const float*)d_in[6];
    float* out = (float*)d_out;

    cudaFuncSetAttribute(conv_kernel, cudaFuncAttributeMaxDynamicSharedMemorySize, SMEM_TOTAL);
    conv_kernel<<<(Bn/2)*Cc, NTHREADS, SMEM_TOTAL>>>(x, w_large, w_small);
    stats_kernel<<<(Cc + 127)/128, 128>>>(gammaL, betaL, gammaS, betaS);
    const int total4 = Bn*Cc*HW/4;
    norm_kernel<<<(total4 + 255)/256, 256>>>(out);
}